// round 12
// baseline (speedup 1.0000x reference)
#include <cuda_runtime.h>
#include <cuda_fp16.h>
#include <cstdint>
#include <math.h>

#define W_LEN   1024
#define BSZ     16
#define EMBED   512
#define NHEADS  8
#define HEAD_DIM 64
#define M_ROWS  (W_LEN*BSZ)      /* 16384 */
#define QKV_N   (3*EMBED)        /* 1536  */
#define KDIM    512

// ---------------- scratch (__device__ globals: no-alloc rule) ----------------
__device__ __align__(256) __half g_xh[M_ROWS * EMBED];    // LN out fp16
__device__ __align__(256) __half g_wh[QKV_N * EMBED];     // in_w fp16
__device__ __align__(256) __half g_owh[EMBED * EMBED];    // out_w fp16
__device__ __align__(256) __half g_attnh[M_ROWS * EMBED]; // attn out fp16
#define BHWD (BSZ*NHEADS*W_LEN*HEAD_DIM)
__device__ __align__(256) __half g_qh[BHWD];              // Q (scaled by 0.125*log2e)
__device__ __align__(256) __half g_kh[BHWD];              // K
__device__ __align__(256) __half g_vh[BHWD];              // V

// ---------------- helpers ----------------
__device__ __forceinline__ uint32_t smem_u32(const void* p) {
    uint32_t a;
    asm("{ .reg .u64 t; cvta.to.shared.u64 t, %1; cvt.u32.u64 %0, t; }" : "=r"(a) : "l"(p));
    return a;
}
__device__ __forceinline__ uint32_t pack_h2(float x, float y) {
    __half2 t = __floats2half2_rn(x, y);
    return *reinterpret_cast<uint32_t*>(&t);
}
__device__ __forceinline__ void ldmatrix_x4(uint32_t* r, uint32_t addr) {
    asm volatile("ldmatrix.sync.aligned.m8n8.x4.shared.b16 {%0,%1,%2,%3}, [%4];"
                 : "=r"(r[0]), "=r"(r[1]), "=r"(r[2]), "=r"(r[3]) : "r"(addr));
}
__device__ __forceinline__ void ldmatrix_x4_trans(uint32_t* r, uint32_t addr) {
    asm volatile("ldmatrix.sync.aligned.m8n8.x4.trans.shared.b16 {%0,%1,%2,%3}, [%4];"
                 : "=r"(r[0]), "=r"(r[1]), "=r"(r[2]), "=r"(r[3]) : "r"(addr));
}
__device__ __forceinline__ void mma16816(float* c, const uint32_t* a, uint32_t b0, uint32_t b1) {
    asm volatile("mma.sync.aligned.m16n8k16.row.col.f32.f16.f16.f32 "
                 "{%0,%1,%2,%3}, {%4,%5,%6,%7}, {%8,%9}, {%0,%1,%2,%3};"
                 : "+f"(c[0]), "+f"(c[1]), "+f"(c[2]), "+f"(c[3])
                 : "r"(a[0]), "r"(a[1]), "r"(a[2]), "r"(a[3]), "r"(b0), "r"(b1));
}
#define CP_ASYNC16(dst, src) \
    asm volatile("cp.async.cg.shared.global [%0], [%1], 16;" :: "r"(dst), "l"(src))
#define CP_COMMIT() asm volatile("cp.async.commit_group;" ::: "memory")
#define CP_WAIT(n)  asm volatile("cp.async.wait_group %0;" :: "n"(n) : "memory")

#define SWZ128(row, g) ((row) * 128 + ((((g) ^ (row)) & 7) << 4))
#define QSCALE 0.1803368801f      /* 0.125 * log2(e) */

// ---------------------------------------------------------------- LayerNorm
__global__ void __launch_bounds__(256) ln_kernel(const float* __restrict__ feat,
                                                 const float* __restrict__ gam,
                                                 const float* __restrict__ bet) {
    int row = blockIdx.x;
    int t = threadIdx.x;
    const float2 v = ((const float2*)(feat + (size_t)row * EMBED))[t];
    __shared__ float red[8];

    float s = v.x + v.y;
    #pragma unroll
    for (int o = 16; o; o >>= 1) s += __shfl_xor_sync(0xffffffffu, s, o);
    if ((t & 31) == 0) red[t >> 5] = s;
    __syncthreads();
    float tot = 0.f;
    #pragma unroll
    for (int i = 0; i < 8; i++) tot += red[i];
    float mu = tot * (1.f / EMBED);
    __syncthreads();

    float dx = v.x - mu, dy = v.y - mu;
    float s2 = dx * dx + dy * dy;
    #pragma unroll
    for (int o = 16; o; o >>= 1) s2 += __shfl_xor_sync(0xffffffffu, s2, o);
    if ((t & 31) == 0) red[t >> 5] = s2;
    __syncthreads();
    float var = 0.f;
    #pragma unroll
    for (int i = 0; i < 8; i++) var += red[i];
    float rstd = rsqrtf(var * (1.f / EMBED) + 1e-5f);

    float2 g2 = ((const float2*)gam)[t];
    float2 b2 = ((const float2*)bet)[t];
    float ox = dx * rstd * g2.x + b2.x;
    float oy = dy * rstd * g2.y + b2.y;
    *(__half2*)&g_xh[(size_t)row * EMBED + 2 * t] = __floats2half2_rn(ox, oy);
}

// ---------------------------------------------- weights fp32 -> fp16
__global__ void wconv_kernel(const float* __restrict__ src, __half* __restrict__ dst,
                             int total) {
    int i = blockIdx.x * 256 + threadIdx.x;
    if (i < total) dst[i] = __float2half(src[i]);
}

// --------------------------------------- fp16 mma GEMM  C = A * B^T
// MODE 1: C = acc + bias + resid (fp32). MODE 2: QKV split-write (all fp16).
#define NCHUNK (KDIM / 64)        /* 8 */
#define ABUF 16384
#define GEMM_SMEM (4 * ABUF)      /* 64KB */

template <int MODE>
__global__ void __launch_bounds__(256, 2) gemm_mma(const __half* __restrict__ A,
                                                   const __half* __restrict__ B,
                                                   const float* __restrict__ bias,
                                                   const float* __restrict__ resid,
                                                   float* __restrict__ C, int N) {
    extern __shared__ __align__(1024) char smem[];
    uint32_t sb = smem_u32(smem);
    int tid = threadIdx.x;
    int lid = tid & 31, wid = tid >> 5;
    int wm = wid & 1, wn = wid >> 1;
    int m0 = blockIdx.y * 128, n0 = blockIdx.x * 128;

    const __half* Ablk = A + (size_t)m0 * KDIM;
    const __half* Bblk = B + (size_t)n0 * KDIM;

    float acc[4][4][4];
    #pragma unroll
    for (int i = 0; i < 4; i++)
        #pragma unroll
        for (int j = 0; j < 4; j++)
            #pragma unroll
            for (int k = 0; k < 4; k++) acc[i][j][k] = 0.f;

    auto load_chunk = [&](int c, int s) {
        int koff = c * 64;
        uint32_t abase = sb + s * ABUF;
        uint32_t bbase = sb + 2 * ABUF + s * ABUF;
        #pragma unroll
        for (int i = 0; i < 4; i++) {
            int idx = tid + i * 256;
            int row = idx >> 3, g = idx & 7;
            CP_ASYNC16(abase + SWZ128(row, g), Ablk + (size_t)row * KDIM + koff + g * 8);
        }
        #pragma unroll
        for (int i = 0; i < 4; i++) {
            int idx = tid + i * 256;
            int row = idx >> 3, g = idx & 7;
            CP_ASYNC16(bbase + SWZ128(row, g), Bblk + (size_t)row * KDIM + koff + g * 8);
        }
        CP_COMMIT();
    };

    load_chunk(0, 0);

    for (int c = 0; c < NCHUNK; c++) {
        int s = c & 1;
        if (c + 1 < NCHUNK) { load_chunk(c + 1, s ^ 1); CP_WAIT(1); }
        else                { CP_WAIT(0); }
        __syncthreads();

        uint32_t abase = sb + s * ABUF;
        uint32_t bbase = sb + 2 * ABUF + s * ABUF;
        #pragma unroll
        for (int ks = 0; ks < 4; ks++) {
            uint32_t afr[4][4];
            #pragma unroll
            for (int mi = 0; mi < 4; mi++) {
                int row = wm * 64 + mi * 16 + (lid & 15);
                int g = ks * 2 + (lid >> 4);
                ldmatrix_x4(afr[mi], abase + SWZ128(row, g));
            }
            uint32_t bfr[2][4];
            #pragma unroll
            for (int nf = 0; nf < 2; nf++) {
                int row = wn * 32 + nf * 16 + (lid & 7) + ((lid & 16) >> 1);
                int g = ks * 2 + ((lid & 8) >> 3);
                ldmatrix_x4(bfr[nf], bbase + SWZ128(row, g));
            }
            #pragma unroll
            for (int mi = 0; mi < 4; mi++)
                #pragma unroll
                for (int nj = 0; nj < 4; nj++) {
                    const uint32_t* b = bfr[nj >> 1];
                    mma16816(acc[mi][nj], afr[mi], b[(nj & 1) * 2], b[(nj & 1) * 2 + 1]);
                }
        }
        __syncthreads();
    }

    if (MODE == 1) {
        #pragma unroll
        for (int mi = 0; mi < 4; mi++) {
            int mA = m0 + wm * 64 + mi * 16 + (lid >> 2);
            #pragma unroll
            for (int nj = 0; nj < 4; nj++) {
                int n = n0 + wn * 32 + nj * 8 + 2 * (lid & 3);
                float bx = bias[n], by = bias[n + 1];
                float2 v0 = make_float2(acc[mi][nj][0] + bx, acc[mi][nj][1] + by);
                float2 v1 = make_float2(acc[mi][nj][2] + bx, acc[mi][nj][3] + by);
                float2 r0 = *(const float2*)&resid[(size_t)mA * N + n];
                float2 r1 = *(const float2*)&resid[(size_t)(mA + 8) * N + n];
                v0.x += r0.x; v0.y += r0.y; v1.x += r1.x; v1.y += r1.y;
                *(float2*)&C[(size_t)mA * N + n] = v0;
                *(float2*)&C[(size_t)(mA + 8) * N + n] = v1;
            }
        }
    } else {
        #pragma unroll
        for (int mi = 0; mi < 4; mi++) {
            int mbase = m0 + wm * 64 + mi * 16 + (lid >> 2);
            #pragma unroll
            for (int nj = 0; nj < 4; nj++) {
                int n = n0 + wn * 32 + nj * 8 + 2 * (lid & 3);
                int region = n >> 9;
                int hh = (n & 511) >> 6;
                int d = n & 63;
                float bx = bias[n], by = bias[n + 1];
                __half* dst = (region == 0) ? g_qh : (region == 1) ? g_kh : g_vh;
                float scl = (region == 0) ? QSCALE : 1.0f;
                #pragma unroll
                for (int rr = 0; rr < 2; rr++) {
                    int m = mbase + rr * 8;
                    int w = m >> 4, b = m & 15;
                    float vx = (acc[mi][nj][rr * 2 + 0] + bx) * scl;
                    float vy = (acc[mi][nj][rr * 2 + 1] + by) * scl;
                    size_t off = ((size_t)(b * 8 + hh) * W_LEN + w) * HEAD_DIM + d;
                    *(__half2*)&dst[off] = __floats2half2_rn(vx, vy);
                }
            }
        }
    }
}

// ------------------------------------------------------------- Attention
// 256 threads (8 warps), 128-query tile, 64-key blocks double-buffered.
// Everything fp16 HMMA; softmax in exp2 domain (log2e folded into Q scale).
#define AT_Q 0                   /* 16KB fp16 128x64 */
#define AT_K 16384               /* 2 x 8KB fp16     */
#define AT_V 32768               /* 2 x 8KB fp16     */
#define ATTN_SMEM 49152

__global__ void __launch_bounds__(256, 2) attn_kernel() {
    extern __shared__ __align__(1024) char smem[];
    uint32_t sb = smem_u32(smem);
    int tid = threadIdx.x;
    int lid = tid & 31, wid = tid >> 5;
    int bh = blockIdx.y;
    int q0 = blockIdx.x * 128;
    size_t gb = (size_t)bh * (W_LEN * HEAD_DIM);

    auto ldQ = [&](uint32_t dstbase, const __half* src, int row0) {
        #pragma unroll
        for (int i = 0; i < 4; i++) {
            int idx = tid + i * 256;
            int row = idx >> 3, g = idx & 7;
            CP_ASYNC16(dstbase + SWZ128(row, g),
                       src + gb + (size_t)(row0 + row) * HEAD_DIM + g * 8);
        }
    };
    auto ldKV = [&](uint32_t dstbase, const __half* src, int row0) {
        #pragma unroll
        for (int i = 0; i < 2; i++) {
            int idx = tid + i * 256;
            int row = idx >> 3, g = idx & 7;
            CP_ASYNC16(dstbase + SWZ128(row, g),
                       src + gb + (size_t)(row0 + row) * HEAD_DIM + g * 8);
        }
    };

    ldQ(sb + AT_Q, g_qh, q0);
    ldKV(sb + AT_K, g_kh, 0);
    ldKV(sb + AT_V, g_vh, 0);
    CP_COMMIT();

    float o[8][4];
    #pragma unroll
    for (int i = 0; i < 8; i++)
        #pragma unroll
        for (int j = 0; j < 4; j++) o[i][j] = 0.f;
    float mrow[2] = {-1e30f, -1e30f};
    float lrow[2] = {0.f, 0.f};

    for (int kt = 0; kt < 16; kt++) {
        int s = kt & 1;
        if (kt < 15) {
            int r0 = (kt + 1) * 64;
            ldKV(sb + AT_K + (s ^ 1) * 8192, g_kh, r0);
            ldKV(sb + AT_V + (s ^ 1) * 8192, g_vh, r0);
            CP_COMMIT();
            CP_WAIT(1);
        } else {
            CP_WAIT(0);
        }
        __syncthreads();

        uint32_t kbase = sb + AT_K + s * 8192;
        uint32_t vbase = sb + AT_V + s * 8192;

        // ---- S = Q K^T (fp16 HMMA, scores already in log2 units) ----
        float sc[8][4];
        #pragma unroll
        for (int i = 0; i < 8; i++)
            #pragma unroll
            for (int j = 0; j < 4; j++) sc[i][j] = 0.f;

        #pragma unroll
        for (int ks = 0; ks < 4; ks++) {            // 4 k16-steps over d=64
            uint32_t afr[4];
            {
                int row = wid * 16 + (lid & 15);
                int g = ks * 2 + (lid >> 4);
                ldmatrix_x4(afr, sb + AT_Q + SWZ128(row, g));
            }
            #pragma unroll
            for (int nf = 0; nf < 4; nf++) {
                uint32_t bfr[4];
                int row = nf * 16 + (lid & 7) + ((lid & 16) >> 1);
                int g = ks * 2 + ((lid & 8) >> 3);
                ldmatrix_x4(bfr, kbase + SWZ128(row, g));
                mma16816(sc[nf * 2 + 0], afr, bfr[0], bfr[1]);
                mma16816(sc[nf * 2 + 1], afr, bfr[2], bfr[3]);
            }
        }

        // ---- online softmax (exp2 domain) ----
        float mx0 = -1e30f, mx1 = -1e30f;
        #pragma unroll
        for (int j = 0; j < 8; j++) {
            mx0 = fmaxf(mx0, fmaxf(sc[j][0], sc[j][1]));
            mx1 = fmaxf(mx1, fmaxf(sc[j][2], sc[j][3]));
        }
        #pragma unroll
        for (int ofs = 1; ofs <= 2; ofs <<= 1) {
            mx0 = fmaxf(mx0, __shfl_xor_sync(0xffffffffu, mx0, ofs));
            mx1 = fmaxf(mx1, __shfl_xor_sync(0xffffffffu, mx1, ofs));
        }
        float mn0 = fmaxf(mrow[0], mx0), mn1 = fmaxf(mrow[1], mx1);
        float corr0 = exp2f(mrow[0] - mn0), corr1 = exp2f(mrow[1] - mn1);
        mrow[0] = mn0; mrow[1] = mn1;

        float sum0 = 0.f, sum1 = 0.f;
        #pragma unroll
        for (int j = 0; j < 8; j++) {
            sc[j][0] = exp2f(sc[j][0] - mn0);
            sc[j][1] = exp2f(sc[j][1] - mn0);
            sc[j][2] = exp2f(sc[j][2] - mn1);
            sc[j][3] = exp2f(sc[j][3] - mn1);
            sum0 += sc[j][0] + sc[j][1];
            sum1 += sc[j][2] + sc[j][3];
        }
        #pragma unroll
        for (int ofs = 1; ofs <= 2; ofs <<= 1) {
            sum0 += __shfl_xor_sync(0xffffffffu, sum0, ofs);
            sum1 += __shfl_xor_sync(0xffffffffu, sum1, ofs);
        }
        lrow[0] = lrow[0] * corr0 + sum0;
        lrow[1] = lrow[1] * corr1 + sum1;
        if (__any_sync(0xffffffffu, (corr0 != 1.f) | (corr1 != 1.f))) {
            #pragma unroll
            for (int nd = 0; nd < 8; nd++) {
                o[nd][0] *= corr0; o[nd][1] *= corr0;
                o[nd][2] *= corr1; o[nd][3] *= corr1;
            }
        }

        // ---- P frags (fp16 RN) ----
        uint32_t ph[4][4];
        #pragma unroll
        for (int kc = 0; kc < 4; kc++) {
            int j0 = kc * 2, j1 = kc * 2 + 1;
            ph[kc][0] = pack_h2(sc[j0][0], sc[j0][1]);
            ph[kc][1] = pack_h2(sc[j0][2], sc[j0][3]);
            ph[kc][2] = pack_h2(sc[j1][0], sc[j1][1]);
            ph[kc][3] = pack_h2(sc[j1][2], sc[j1][3]);
        }

        // ---- O += P V (fp16) ----
        #pragma unroll
        for (int kc = 0; kc < 4; kc++) {
            #pragma unroll
            for (int np = 0; np < 4; np++) {
                uint32_t vhf[4];
                int row = kc * 16 + (lid & 7) + ((lid >> 3) & 1) * 8;
                int c16 = np * 2 + ((lid >> 4) & 1);
                ldmatrix_x4_trans(vhf, vbase + ((row * 128) + (((c16 ^ (row & 7)) & 7) << 4)));
                mma16816(o[np * 2 + 0], ph[kc], vhf[0], vhf[1]);
                mma16816(o[np * 2 + 1], ph[kc], vhf[2], vhf[3]);
            }
        }
        __syncthreads();
    }

    // ---- epilogue: normalize, write fp16 [m][E] ----
    float inv0 = 1.f / lrow[0], inv1 = 1.f / lrow[1];
    int b = bh >> 3, h = bh & 7;
    int r0 = lid >> 2, c0 = (lid & 3) * 2;
    #pragma unroll
    for (int nd = 0; nd < 8; nd++) {
        int col = h * HEAD_DIM + nd * 8 + c0;
        #pragma unroll
        for (int rr = 0; rr < 2; rr++) {
            int w = q0 + wid * 16 + r0 + rr * 8;
            int m = w * BSZ + b;
            float inv = rr ? inv1 : inv0;
            float vx = o[nd][rr * 2 + 0] * inv;
            float vy = o[nd][rr * 2 + 1] * inv;
            *(__half2*)&g_attnh[(size_t)m * EMBED + col] = __floats2half2_rn(vx, vy);
        }
    }
}

// ---------------------------------------------------------------- launcher
extern "C" void kernel_launch(void* const* d_in, const int* in_sizes, int n_in,
                              void* d_out, int out_size) {
    const float* feat  = (const float*)d_in[0];
    const float* in_w  = (const float*)d_in[1];
    const float* in_b  = (const float*)d_in[2];
    const float* out_w = (const float*)d_in[3];
    const float* out_b = (const float*)d_in[4];
    const float* ln_g  = (const float*)d_in[5];
    const float* ln_b  = (const float*)d_in[6];
    float* out = (float*)d_out;

    __half *xh, *wh, *owh, *attnh;
    cudaGetSymbolAddress((void**)&xh,    g_xh);
    cudaGetSymbolAddress((void**)&wh,    g_wh);
    cudaGetSymbolAddress((void**)&owh,   g_owh);
    cudaGetSymbolAddress((void**)&attnh, g_attnh);

    cudaFuncSetAttribute(gemm_mma<1>, cudaFuncAttributeMaxDynamicSharedMemorySize, GEMM_SMEM);
    cudaFuncSetAttribute(gemm_mma<2>, cudaFuncAttributeMaxDynamicSharedMemorySize, GEMM_SMEM);
    cudaFuncSetAttribute(attn_kernel, cudaFuncAttributeMaxDynamicSharedMemorySize, ATTN_SMEM);

    // 1. LayerNorm -> fp16
    ln_kernel<<<M_ROWS, 256>>>(feat, ln_g, ln_b);

    // 2. weights -> fp16
    wconv_kernel<<<(QKV_N * EMBED + 255) / 256, 256>>>(in_w, wh, QKV_N * EMBED);
    wconv_kernel<<<(EMBED * EMBED + 255) / 256, 256>>>(out_w, owh, EMBED * EMBED);

    // 3. QKV projection (fp16 mma) -> q/k/v fp16 in [bh][w][d]
    gemm_mma<2><<<dim3(QKV_N / 128, M_ROWS / 128), 256, GEMM_SMEM>>>(
        xh, wh, in_b, nullptr, nullptr, QKV_N);

    // 4. Attention (all fp16 HMMA, exp2 softmax) -> fp16
    attn_kernel<<<dim3(W_LEN / 128, BSZ * NHEADS), 256, ATTN_SMEM>>>();

    // 5. Out projection (fp16 mma) + bias + residual -> d_out
    gemm_mma<1><<<dim3(EMBED / 128, M_ROWS / 128), 256, GEMM_SMEM>>>(
        attnh, owh, out_b, feat, out, EMBED);
}

// round 16
// speedup vs baseline: 1.3430x; 1.3430x over previous
#include <cuda_runtime.h>
#include <cuda_bf16.h>
#include <cstdint>
#include <math.h>

#define W_LEN   1024
#define BSZ     16
#define EMBED   512
#define NHEADS  8
#define HEAD_DIM 64
#define M_ROWS  (W_LEN*BSZ)      /* 16384 */
#define QKV_N   (3*EMBED)        /* 1536  */
#define KDIM    512

// ---------------- scratch (__device__ globals: no-alloc rule) ----------------
__device__ __align__(256) __nv_bfloat16 g_xh[M_ROWS * EMBED];    // LN out bf16
__device__ __align__(256) __nv_bfloat16 g_wh[QKV_N * EMBED];     // in_w bf16
__device__ __align__(256) __nv_bfloat16 g_owh[EMBED * EMBED];    // out_w bf16
__device__ __align__(256) __nv_bfloat16 g_attnh[M_ROWS * EMBED]; // attn out bf16
#define BHWD (BSZ*NHEADS*W_LEN*HEAD_DIM)
__device__ __align__(256) float g_qf[BHWD];                      // Q (x 0.125*log2e, tf32)
__device__ __align__(256) float g_kf[BHWD];                      // K (tf32)
__device__ __align__(256) __nv_bfloat16 g_vh[BHWD];              // V (bf16 RN)

// ---------------- helpers ----------------
__device__ __forceinline__ uint32_t smem_u32(const void* p) {
    uint32_t a;
    asm("{ .reg .u64 t; cvta.to.shared.u64 t, %1; cvt.u32.u64 %0, t; }" : "=r"(a) : "l"(p));
    return a;
}
__device__ __forceinline__ float to_tf32(float x) {
    float y;
    asm("cvt.rna.tf32.f32 %0, %1;" : "=f"(y) : "f"(x));
    return y;
}
__device__ __forceinline__ float fast_ex2(float x) {
    float y;
    asm("ex2.approx.f32 %0, %1;" : "=f"(y) : "f"(x));
    return y;
}
__device__ __forceinline__ uint32_t pack_bf16(float x, float y) {
    __nv_bfloat162 t = __floats2bfloat162_rn(x, y);
    return *reinterpret_cast<uint32_t*>(&t);
}
__device__ __forceinline__ void ldmatrix_x4(uint32_t* r, uint32_t addr) {
    asm volatile("ldmatrix.sync.aligned.m8n8.x4.shared.b16 {%0,%1,%2,%3}, [%4];"
                 : "=r"(r[0]), "=r"(r[1]), "=r"(r[2]), "=r"(r[3]) : "r"(addr));
}
__device__ __forceinline__ void ldmatrix_x4_trans(uint32_t* r, uint32_t addr) {
    asm volatile("ldmatrix.sync.aligned.m8n8.x4.trans.shared.b16 {%0,%1,%2,%3}, [%4];"
                 : "=r"(r[0]), "=r"(r[1]), "=r"(r[2]), "=r"(r[3]) : "r"(addr));
}
__device__ __forceinline__ void mma16816(float* c, const uint32_t* a, uint32_t b0, uint32_t b1) {
    asm volatile("mma.sync.aligned.m16n8k16.row.col.f32.bf16.bf16.f32 "
                 "{%0,%1,%2,%3}, {%4,%5,%6,%7}, {%8,%9}, {%0,%1,%2,%3};"
                 : "+f"(c[0]), "+f"(c[1]), "+f"(c[2]), "+f"(c[3])
                 : "r"(a[0]), "r"(a[1]), "r"(a[2]), "r"(a[3]), "r"(b0), "r"(b1));
}
__device__ __forceinline__ void mma_tf32(float* c, const uint32_t* a, uint32_t b0, uint32_t b1) {
    asm volatile("mma.sync.aligned.m16n8k8.row.col.f32.tf32.tf32.f32 "
                 "{%0,%1,%2,%3}, {%4,%5,%6,%7}, {%8,%9}, {%0,%1,%2,%3};"
                 : "+f"(c[0]), "+f"(c[1]), "+f"(c[2]), "+f"(c[3])
                 : "r"(a[0]), "r"(a[1]), "r"(a[2]), "r"(a[3]), "r"(b0), "r"(b1));
}
#define CP_ASYNC16(dst, src) \
    asm volatile("cp.async.cg.shared.global [%0], [%1], 16;" :: "r"(dst), "l"(src))
#define CP_COMMIT() asm volatile("cp.async.commit_group;" ::: "memory")
#define CP_WAIT(n)  asm volatile("cp.async.wait_group %0;" :: "n"(n) : "memory")

#define SWZ128(row, g) ((row) * 128 + ((((g) ^ (row)) & 7) << 4))
#define SWZ256(row, g) ((row) * 256 + (((g) & 8) << 4) + ((((g) ^ (row)) & 7) << 4))
#define QSCALE 0.1803368801f      /* 0.125 * log2(e) */

// ---------------------------------------------------------------- LayerNorm
__global__ void __launch_bounds__(256) ln_kernel(const float* __restrict__ feat,
                                                 const float* __restrict__ gam,
                                                 const float* __restrict__ bet) {
    int row = blockIdx.x;
    int t = threadIdx.x;
    const float2 v = ((const float2*)(feat + (size_t)row * EMBED))[t];
    __shared__ float red[8];

    float s = v.x + v.y;
    #pragma unroll
    for (int o = 16; o; o >>= 1) s += __shfl_xor_sync(0xffffffffu, s, o);
    if ((t & 31) == 0) red[t >> 5] = s;
    __syncthreads();
    float tot = 0.f;
    #pragma unroll
    for (int i = 0; i < 8; i++) tot += red[i];
    float mu = tot * (1.f / EMBED);
    __syncthreads();

    float dx = v.x - mu, dy = v.y - mu;
    float s2 = dx * dx + dy * dy;
    #pragma unroll
    for (int o = 16; o; o >>= 1) s2 += __shfl_xor_sync(0xffffffffu, s2, o);
    if ((t & 31) == 0) red[t >> 5] = s2;
    __syncthreads();
    float var = 0.f;
    #pragma unroll
    for (int i = 0; i < 8; i++) var += red[i];
    float rstd = rsqrtf(var * (1.f / EMBED) + 1e-5f);

    float2 g2 = ((const float2*)gam)[t];
    float2 b2 = ((const float2*)bet)[t];
    float ox = dx * rstd * g2.x + b2.x;
    float oy = dy * rstd * g2.y + b2.y;
    *(__nv_bfloat162*)&g_xh[(size_t)row * EMBED + 2 * t] = __floats2bfloat162_rn(ox, oy);
}

// ------------------------------- both weight tensors fp32 -> bf16, one launch
#define W1 (QKV_N * EMBED)
#define W2 (EMBED * EMBED)
__global__ void wconv_kernel(const float* __restrict__ src1, const float* __restrict__ src2) {
    int i = blockIdx.x * 256 + threadIdx.x;
    if (i < W1) g_wh[i] = __float2bfloat16(src1[i]);
    else if (i < W1 + W2) g_owh[i - W1] = __float2bfloat16(src2[i - W1]);
}

// --------------------------------------- bf16 mma GEMM  C = A * B^T
// MODE 1: C = acc + bias + resid (fp32). MODE 2: QKV split-write.
#define NCHUNK (KDIM / 64)        /* 8 */
#define ABUF 16384
#define GEMM_SMEM (4 * ABUF)      /* 64KB */

template <int MODE>
__global__ void __launch_bounds__(256, 2) gemm_mma(const __nv_bfloat16* __restrict__ A,
                                                   const __nv_bfloat16* __restrict__ B,
                                                   const float* __restrict__ bias,
                                                   const float* __restrict__ resid,
                                                   float* __restrict__ C, int N) {
    extern __shared__ __align__(1024) char smem[];
    uint32_t sb = smem_u32(smem);
    int tid = threadIdx.x;
    int lid = tid & 31, wid = tid >> 5;
    int wm = wid & 1, wn = wid >> 1;
    int m0 = blockIdx.y * 128, n0 = blockIdx.x * 128;

    const __nv_bfloat16* Ablk = A + (size_t)m0 * KDIM;
    const __nv_bfloat16* Bblk = B + (size_t)n0 * KDIM;

    float acc[4][4][4];
    #pragma unroll
    for (int i = 0; i < 4; i++)
        #pragma unroll
        for (int j = 0; j < 4; j++)
            #pragma unroll
            for (int k = 0; k < 4; k++) acc[i][j][k] = 0.f;

    auto load_chunk = [&](int c, int s) {
        int koff = c * 64;
        uint32_t abase = sb + s * ABUF;
        uint32_t bbase = sb + 2 * ABUF + s * ABUF;
        #pragma unroll
        for (int i = 0; i < 4; i++) {
            int idx = tid + i * 256;
            int row = idx >> 3, g = idx & 7;
            CP_ASYNC16(abase + SWZ128(row, g), Ablk + (size_t)row * KDIM + koff + g * 8);
        }
        #pragma unroll
        for (int i = 0; i < 4; i++) {
            int idx = tid + i * 256;
            int row = idx >> 3, g = idx & 7;
            CP_ASYNC16(bbase + SWZ128(row, g), Bblk + (size_t)row * KDIM + koff + g * 8);
        }
        CP_COMMIT();
    };

    load_chunk(0, 0);

    for (int c = 0; c < NCHUNK; c++) {
        int s = c & 1;
        if (c + 1 < NCHUNK) { load_chunk(c + 1, s ^ 1); CP_WAIT(1); }
        else                { CP_WAIT(0); }
        __syncthreads();

        uint32_t abase = sb + s * ABUF;
        uint32_t bbase = sb + 2 * ABUF + s * ABUF;
        #pragma unroll
        for (int ks = 0; ks < 4; ks++) {
            uint32_t afr[4][4];
            #pragma unroll
            for (int mi = 0; mi < 4; mi++) {
                int row = wm * 64 + mi * 16 + (lid & 15);
                int g = ks * 2 + (lid >> 4);
                ldmatrix_x4(afr[mi], abase + SWZ128(row, g));
            }
            uint32_t bfr[2][4];
            #pragma unroll
            for (int nf = 0; nf < 2; nf++) {
                int row = wn * 32 + nf * 16 + (lid & 7) + ((lid & 16) >> 1);
                int g = ks * 2 + ((lid & 8) >> 3);
                ldmatrix_x4(bfr[nf], bbase + SWZ128(row, g));
            }
            #pragma unroll
            for (int mi = 0; mi < 4; mi++)
                #pragma unroll
                for (int nj = 0; nj < 4; nj++) {
                    const uint32_t* b = bfr[nj >> 1];
                    mma16816(acc[mi][nj], afr[mi], b[(nj & 1) * 2], b[(nj & 1) * 2 + 1]);
                }
        }
        __syncthreads();
    }

    if (MODE == 1) {
        #pragma unroll
        for (int mi = 0; mi < 4; mi++) {
            int mA = m0 + wm * 64 + mi * 16 + (lid >> 2);
            #pragma unroll
            for (int nj = 0; nj < 4; nj++) {
                int n = n0 + wn * 32 + nj * 8 + 2 * (lid & 3);
                float bx = bias[n], by = bias[n + 1];
                float2 v0 = make_float2(acc[mi][nj][0] + bx, acc[mi][nj][1] + by);
                float2 v1 = make_float2(acc[mi][nj][2] + bx, acc[mi][nj][3] + by);
                float2 r0 = *(const float2*)&resid[(size_t)mA * N + n];
                float2 r1 = *(const float2*)&resid[(size_t)(mA + 8) * N + n];
                v0.x += r0.x; v0.y += r0.y; v1.x += r1.x; v1.y += r1.y;
                *(float2*)&C[(size_t)mA * N + n] = v0;
                *(float2*)&C[(size_t)(mA + 8) * N + n] = v1;
            }
        }
    } else {
        #pragma unroll
        for (int mi = 0; mi < 4; mi++) {
            int mbase = m0 + wm * 64 + mi * 16 + (lid >> 2);
            #pragma unroll
            for (int nj = 0; nj < 4; nj++) {
                int n = n0 + wn * 32 + nj * 8 + 2 * (lid & 3);
                int region = n >> 9;
                int hh = (n & 511) >> 6;
                int d = n & 63;
                float bx = bias[n], by = bias[n + 1];
                #pragma unroll
                for (int rr = 0; rr < 2; rr++) {
                    int m = mbase + rr * 8;
                    int w = m >> 4, b = m & 15;
                    float vx = acc[mi][nj][rr * 2 + 0] + bx;
                    float vy = acc[mi][nj][rr * 2 + 1] + by;
                    size_t off = ((size_t)(b * 8 + hh) * W_LEN + w) * HEAD_DIM + d;
                    if (region == 0) {
                        // fold softmax scale AND log2(e) into Q
                        *(float2*)&g_qf[off] =
                            make_float2(to_tf32(vx * QSCALE), to_tf32(vy * QSCALE));
                    } else if (region == 1) {
                        *(float2*)&g_kf[off] = make_float2(to_tf32(vx), to_tf32(vy));
                    } else {
                        *(__nv_bfloat162*)&g_vh[off] = __floats2bfloat162_rn(vx, vy);
                    }
                }
            }
        }
    }
}

// ------------------------------------------------------------- Attention
// 256 threads (8 warps), 128-query tile, 64-key blocks double-buffered.
// QK^T tf32 (scores in log2 domain), ex2.approx softmax, PV bf16 1-term.
#define AT_Q 0                   /* 32KB fp32 128x64 */
#define AT_K 32768               /* 2 x 16KB fp32    */
#define AT_V 65536               /* 2 x 8KB bf16     */
#define ATTN_SMEM 81920

__global__ void __launch_bounds__(256, 2) attn_kernel() {
    extern __shared__ __align__(1024) char smem[];
    uint32_t sb = smem_u32(smem);
    int tid = threadIdx.x;
    int lid = tid & 31, wid = tid >> 5;
    int bh = blockIdx.y;
    int q0 = blockIdx.x * 128;
    size_t gb = (size_t)bh * (W_LEN * HEAD_DIM);

    auto ldQ = [&](uint32_t dstbase, const float* src, int row0) {
        #pragma unroll
        for (int i = 0; i < 8; i++) {
            int idx = tid + i * 256;
            int row = idx >> 4, g = idx & 15;
            CP_ASYNC16(dstbase + SWZ256(row, g),
                       src + gb + (size_t)(row0 + row) * HEAD_DIM + g * 4);
        }
    };
    auto ldK = [&](uint32_t dstbase, const float* src, int row0) {
        #pragma unroll
        for (int i = 0; i < 4; i++) {
            int idx = tid + i * 256;
            int row = idx >> 4, g = idx & 15;
            CP_ASYNC16(dstbase + SWZ256(row, g),
                       src + gb + (size_t)(row0 + row) * HEAD_DIM + g * 4);
        }
    };
    auto ldV = [&](uint32_t dstbase, const __nv_bfloat16* src, int row0) {
        #pragma unroll
        for (int i = 0; i < 2; i++) {
            int idx = tid + i * 256;
            int row = idx >> 3, g = idx & 7;
            CP_ASYNC16(dstbase + SWZ128(row, g),
                       src + gb + (size_t)(row0 + row) * HEAD_DIM + g * 8);
        }
    };

    ldQ(sb + AT_Q, g_qf, q0);
    ldK(sb + AT_K, g_kf, 0);
    ldV(sb + AT_V, g_vh, 0);
    CP_COMMIT();

    float o[8][4];
    #pragma unroll
    for (int i = 0; i < 8; i++)
        #pragma unroll
        for (int j = 0; j < 4; j++) o[i][j] = 0.f;
    float mrow[2] = {-1e30f, -1e30f};
    float lrow[2] = {0.f, 0.f};

    for (int kt = 0; kt < 16; kt++) {
        int s = kt & 1;
        if (kt < 15) {
            int r0 = (kt + 1) * 64;
            ldK(sb + AT_K + (s ^ 1) * 16384, g_kf, r0);
            ldV(sb + AT_V + (s ^ 1) * 8192, g_vh, r0);
            CP_COMMIT();
            CP_WAIT(1);
        } else {
            CP_WAIT(0);
        }
        __syncthreads();

        uint32_t kbase = sb + AT_K + s * 16384;
        uint32_t vbase = sb + AT_V + s * 8192;

        // ---- S = Q K^T (tf32, log2-domain scores) ----
        float sc[8][4];
        #pragma unroll
        for (int i = 0; i < 8; i++)
            #pragma unroll
            for (int j = 0; j < 4; j++) sc[i][j] = 0.f;

        #pragma unroll
        for (int s8 = 0; s8 < 8; s8++) {
            uint32_t afr[4];
            {
                int row = wid * 16 + ((lid >> 3) & 1) * 8 + (lid & 7);
                int g = s8 * 2 + (lid >> 4);
                ldmatrix_x4(afr, sb + AT_Q + SWZ256(row, g));
            }
            #pragma unroll
            for (int nf = 0; nf < 4; nf++) {
                uint32_t bfr[4];
                int row = nf * 16 + ((lid >> 4) << 3) + (lid & 7);
                int g = s8 * 2 + ((lid >> 3) & 1);
                ldmatrix_x4(bfr, kbase + SWZ256(row, g));
                mma_tf32(sc[nf * 2 + 0], afr, bfr[0], bfr[1]);
                mma_tf32(sc[nf * 2 + 1], afr, bfr[2], bfr[3]);
            }
        }

        // ---- online softmax (ex2.approx; log2 domain) ----
        float mx0 = -1e30f, mx1 = -1e30f;
        #pragma unroll
        for (int j = 0; j < 8; j++) {
            mx0 = fmaxf(mx0, fmaxf(sc[j][0], sc[j][1]));
            mx1 = fmaxf(mx1, fmaxf(sc[j][2], sc[j][3]));
        }
        #pragma unroll
        for (int ofs = 1; ofs <= 2; ofs <<= 1) {
            mx0 = fmaxf(mx0, __shfl_xor_sync(0xffffffffu, mx0, ofs));
            mx1 = fmaxf(mx1, __shfl_xor_sync(0xffffffffu, mx1, ofs));
        }
        float mn0 = fmaxf(mrow[0], mx0), mn1 = fmaxf(mrow[1], mx1);
        float corr0 = fast_ex2(mrow[0] - mn0), corr1 = fast_ex2(mrow[1] - mn1);
        mrow[0] = mn0; mrow[1] = mn1;

        float sum0 = 0.f, sum1 = 0.f;
        #pragma unroll
        for (int j = 0; j < 8; j++) {
            sc[j][0] = fast_ex2(sc[j][0] - mn0);
            sc[j][1] = fast_ex2(sc[j][1] - mn0);
            sc[j][2] = fast_ex2(sc[j][2] - mn1);
            sc[j][3] = fast_ex2(sc[j][3] - mn1);
            sum0 += sc[j][0] + sc[j][1];
            sum1 += sc[j][2] + sc[j][3];
        }
        #pragma unroll
        for (int ofs = 1; ofs <= 2; ofs <<= 1) {
            sum0 += __shfl_xor_sync(0xffffffffu, sum0, ofs);
            sum1 += __shfl_xor_sync(0xffffffffu, sum1, ofs);
        }
        lrow[0] = lrow[0] * corr0 + sum0;
        lrow[1] = lrow[1] * corr1 + sum1;
        if (__any_sync(0xffffffffu, (corr0 != 1.f) | (corr1 != 1.f))) {
            #pragma unroll
            for (int nd = 0; nd < 8; nd++) {
                o[nd][0] *= corr0; o[nd][1] *= corr0;
                o[nd][2] *= corr1; o[nd][3] *= corr1;
            }
        }

        // ---- P frags (bf16 RN) ----
        uint32_t ph[4][4];
        #pragma unroll
        for (int kc = 0; kc < 4; kc++) {
            int j0 = kc * 2, j1 = kc * 2 + 1;
            ph[kc][0] = pack_bf16(sc[j0][0], sc[j0][1]);
            ph[kc][1] = pack_bf16(sc[j0][2], sc[j0][3]);
            ph[kc][2] = pack_bf16(sc[j1][0], sc[j1][1]);
            ph[kc][3] = pack_bf16(sc[j1][2], sc[j1][3]);
        }

        // ---- O += P V (bf16 1-term) ----
        #pragma unroll
        for (int kc = 0; kc < 4; kc++) {
            #pragma unroll
            for (int np = 0; np < 4; np++) {
                uint32_t vhf[4];
                int row = kc * 16 + (lid & 7) + ((lid >> 3) & 1) * 8;
                int c16 = np * 2 + ((lid >> 4) & 1);
                ldmatrix_x4_trans(vhf, vbase + ((row * 128) + (((c16 ^ (row & 7)) & 7) << 4)));
                mma16816(o[np * 2 + 0], ph[kc], vhf[0], vhf[1]);
                mma16816(o[np * 2 + 1], ph[kc], vhf[2], vhf[3]);
            }
        }
        __syncthreads();
    }

    // ---- epilogue: normalize, write bf16 [m][E] ----
    float inv0 = 1.f / lrow[0], inv1 = 1.f / lrow[1];
    int b = bh >> 3, h = bh & 7;
    int r0 = lid >> 2, c0 = (lid & 3) * 2;
    #pragma unroll
    for (int nd = 0; nd < 8; nd++) {
        int col = h * HEAD_DIM + nd * 8 + c0;
        #pragma unroll
        for (int rr = 0; rr < 2; rr++) {
            int w = q0 + wid * 16 + r0 + rr * 8;
            int m = w * BSZ + b;
            float inv = rr ? inv1 : inv0;
            float vx = o[nd][rr * 2 + 0] * inv;
            float vy = o[nd][rr * 2 + 1] * inv;
            *(__nv_bfloat162*)&g_attnh[(size_t)m * EMBED + col] = __floats2bfloat162_rn(vx, vy);
        }
    }
}

// ---------------------------------------------------------------- launcher
extern "C" void kernel_launch(void* const* d_in, const int* in_sizes, int n_in,
                              void* d_out, int out_size) {
    const float* feat  = (const float*)d_in[0];
    const float* in_w  = (const float*)d_in[1];
    const float* in_b  = (const float*)d_in[2];
    const float* out_w = (const float*)d_in[3];
    const float* out_b = (const float*)d_in[4];
    const float* ln_g  = (const float*)d_in[5];
    const float* ln_b  = (const float*)d_in[6];
    float* out = (float*)d_out;

    __nv_bfloat16 *xh, *wh, *owh, *attnh;
    cudaGetSymbolAddress((void**)&xh,    g_xh);
    cudaGetSymbolAddress((void**)&wh,    g_wh);
    cudaGetSymbolAddress((void**)&owh,   g_owh);
    cudaGetSymbolAddress((void**)&attnh, g_attnh);

    cudaFuncSetAttribute(gemm_mma<1>, cudaFuncAttributeMaxDynamicSharedMemorySize, GEMM_SMEM);
    cudaFuncSetAttribute(gemm_mma<2>, cudaFuncAttributeMaxDynamicSharedMemorySize, GEMM_SMEM);
    cudaFuncSetAttribute(attn_kernel, cudaFuncAttributeMaxDynamicSharedMemorySize, ATTN_SMEM);

    // 1. LayerNorm -> bf16
    ln_kernel<<<M_ROWS, 256>>>(feat, ln_g, ln_b);

    // 2. both weight tensors -> bf16 (single launch)
    wconv_kernel<<<(W1 + W2 + 255) / 256, 256>>>(in_w, out_w);

    // 3. QKV projection (bf16 mma) -> q/k tf32 (Q pre-scaled by 0.125*log2e), v bf16
    gemm_mma<2><<<dim3(QKV_N / 128, M_ROWS / 128), 256, GEMM_SMEM>>>(
        xh, wh, in_b, nullptr, nullptr, QKV_N);

    // 4. Attention (tf32 QK log2-domain, ex2 softmax, bf16 PV) -> bf16
    attn_kernel<<<dim3(W_LEN / 128, BSZ * NHEADS), 256, ATTN_SMEM>>>();

    // 5. Out projection (bf16 mma) + bias + residual -> d_out
    gemm_mma<1><<<dim3(EMBED / 128, M_ROWS / 128), 256, GEMM_SMEM>>>(
        attnh, owh, out_b, feat, out, EMBED);
}

// round 17
// speedup vs baseline: 1.3442x; 1.0009x over previous
#include <cuda_runtime.h>
#include <cuda_bf16.h>
#include <cstdint>
#include <math.h>

#define W_LEN   1024
#define BSZ     16
#define EMBED   512
#define NHEADS  8
#define HEAD_DIM 64
#define M_ROWS  (W_LEN*BSZ)      /* 16384 */
#define QKV_N   (3*EMBED)        /* 1536  */
#define KDIM    512

// ---------------- scratch (__device__ globals: no-alloc rule) ----------------
__device__ __align__(256) __nv_bfloat16 g_xh[M_ROWS * EMBED];    // LN out bf16
__device__ __align__(256) __nv_bfloat16 g_wh[QKV_N * EMBED];     // in_w bf16
__device__ __align__(256) __nv_bfloat16 g_owh[EMBED * EMBED];    // out_w bf16
__device__ __align__(256) __nv_bfloat16 g_attnh[M_ROWS * EMBED]; // attn out bf16
#define BHWD (BSZ*NHEADS*W_LEN*HEAD_DIM)
__device__ __align__(256) float g_qf[BHWD];                      // Q (x 0.125*log2e, tf32)
__device__ __align__(256) float g_kf[BHWD];                      // K (tf32)
__device__ __align__(256) __nv_bfloat16 g_vh[BHWD];              // V (bf16 RN)

// ---------------- helpers ----------------
__device__ __forceinline__ uint32_t smem_u32(const void* p) {
    uint32_t a;
    asm("{ .reg .u64 t; cvta.to.shared.u64 t, %1; cvt.u32.u64 %0, t; }" : "=r"(a) : "l"(p));
    return a;
}
__device__ __forceinline__ float to_tf32(float x) {
    float y;
    asm("cvt.rna.tf32.f32 %0, %1;" : "=f"(y) : "f"(x));
    return y;
}
__device__ __forceinline__ float fast_ex2(float x) {
    float y;
    asm("ex2.approx.f32 %0, %1;" : "=f"(y) : "f"(x));
    return y;
}
__device__ __forceinline__ uint32_t pack_bf16(float x, float y) {
    __nv_bfloat162 t = __floats2bfloat162_rn(x, y);
    return *reinterpret_cast<uint32_t*>(&t);
}
__device__ __forceinline__ void ldmatrix_x4(uint32_t* r, uint32_t addr) {
    asm volatile("ldmatrix.sync.aligned.m8n8.x4.shared.b16 {%0,%1,%2,%3}, [%4];"
                 : "=r"(r[0]), "=r"(r[1]), "=r"(r[2]), "=r"(r[3]) : "r"(addr));
}
__device__ __forceinline__ void ldmatrix_x4_trans(uint32_t* r, uint32_t addr) {
    asm volatile("ldmatrix.sync.aligned.m8n8.x4.trans.shared.b16 {%0,%1,%2,%3}, [%4];"
                 : "=r"(r[0]), "=r"(r[1]), "=r"(r[2]), "=r"(r[3]) : "r"(addr));
}
__device__ __forceinline__ void mma16816(float* c, const uint32_t* a, uint32_t b0, uint32_t b1) {
    asm volatile("mma.sync.aligned.m16n8k16.row.col.f32.bf16.bf16.f32 "
                 "{%0,%1,%2,%3}, {%4,%5,%6,%7}, {%8,%9}, {%0,%1,%2,%3};"
                 : "+f"(c[0]), "+f"(c[1]), "+f"(c[2]), "+f"(c[3])
                 : "r"(a[0]), "r"(a[1]), "r"(a[2]), "r"(a[3]), "r"(b0), "r"(b1));
}
__device__ __forceinline__ void mma_tf32(float* c, const uint32_t* a, uint32_t b0, uint32_t b1) {
    asm volatile("mma.sync.aligned.m16n8k8.row.col.f32.tf32.tf32.f32 "
                 "{%0,%1,%2,%3}, {%4,%5,%6,%7}, {%8,%9}, {%0,%1,%2,%3};"
                 : "+f"(c[0]), "+f"(c[1]), "+f"(c[2]), "+f"(c[3])
                 : "r"(a[0]), "r"(a[1]), "r"(a[2]), "r"(a[3]), "r"(b0), "r"(b1));
}
#define CP_ASYNC16(dst, src) \
    asm volatile("cp.async.cg.shared.global [%0], [%1], 16;" :: "r"(dst), "l"(src))
#define CP_COMMIT() asm volatile("cp.async.commit_group;" ::: "memory")
#define CP_WAIT(n)  asm volatile("cp.async.wait_group %0;" :: "n"(n) : "memory")

#define SWZ128(row, g) ((row) * 128 + ((((g) ^ (row)) & 7) << 4))
#define SWZ256(row, g) ((row) * 256 + (((g) & 8) << 4) + ((((g) ^ (row)) & 7) << 4))
#define QSCALE 0.1803368801f      /* 0.125 * log2(e) */

// ---------------------------------------------------------------- LayerNorm
__global__ void __launch_bounds__(256) ln_kernel(const float* __restrict__ feat,
                                                 const float* __restrict__ gam,
                                                 const float* __restrict__ bet) {
    int row = blockIdx.x;
    int t = threadIdx.x;
    const float2 v = ((const float2*)(feat + (size_t)row * EMBED))[t];
    __shared__ float red[8];

    float s = v.x + v.y;
    #pragma unroll
    for (int o = 16; o; o >>= 1) s += __shfl_xor_sync(0xffffffffu, s, o);
    if ((t & 31) == 0) red[t >> 5] = s;
    __syncthreads();
    float tot = 0.f;
    #pragma unroll
    for (int i = 0; i < 8; i++) tot += red[i];
    float mu = tot * (1.f / EMBED);
    __syncthreads();

    float dx = v.x - mu, dy = v.y - mu;
    float s2 = dx * dx + dy * dy;
    #pragma unroll
    for (int o = 16; o; o >>= 1) s2 += __shfl_xor_sync(0xffffffffu, s2, o);
    if ((t & 31) == 0) red[t >> 5] = s2;
    __syncthreads();
    float var = 0.f;
    #pragma unroll
    for (int i = 0; i < 8; i++) var += red[i];
    float rstd = rsqrtf(var * (1.f / EMBED) + 1e-5f);

    float2 g2 = ((const float2*)gam)[t];
    float2 b2 = ((const float2*)bet)[t];
    float ox = dx * rstd * g2.x + b2.x;
    float oy = dy * rstd * g2.y + b2.y;
    *(__nv_bfloat162*)&g_xh[(size_t)row * EMBED + 2 * t] = __floats2bfloat162_rn(ox, oy);
}

// ------------------------------- both weight tensors fp32 -> bf16, one launch
#define W1 (QKV_N * EMBED)
#define W2 (EMBED * EMBED)
__global__ void wconv_kernel(const float* __restrict__ src1, const float* __restrict__ src2) {
    int i = blockIdx.x * 256 + threadIdx.x;
    if (i < W1) g_wh[i] = __float2bfloat16(src1[i]);
    else if (i < W1 + W2) g_owh[i - W1] = __float2bfloat16(src2[i - W1]);
}

// --------------------------------------- bf16 mma GEMM  C = A * B^T
// MODE 1: C = acc + bias + resid (fp32). MODE 2: QKV split-write.
#define NCHUNK (KDIM / 64)        /* 8 */
#define ABUF 16384
#define GEMM_SMEM (4 * ABUF)      /* 64KB */

template <int MODE>
__global__ void __launch_bounds__(256, 2) gemm_mma(const __nv_bfloat16* __restrict__ A,
                                                   const __nv_bfloat16* __restrict__ B,
                                                   const float* __restrict__ bias,
                                                   const float* __restrict__ resid,
                                                   float* __restrict__ C, int N) {
    extern __shared__ __align__(1024) char smem[];
    uint32_t sb = smem_u32(smem);
    int tid = threadIdx.x;
    int lid = tid & 31, wid = tid >> 5;
    int wm = wid & 1, wn = wid >> 1;
    int m0 = blockIdx.y * 128, n0 = blockIdx.x * 128;

    const __nv_bfloat16* Ablk = A + (size_t)m0 * KDIM;
    const __nv_bfloat16* Bblk = B + (size_t)n0 * KDIM;

    float acc[4][4][4];
    #pragma unroll
    for (int i = 0; i < 4; i++)
        #pragma unroll
        for (int j = 0; j < 4; j++)
            #pragma unroll
            for (int k = 0; k < 4; k++) acc[i][j][k] = 0.f;

    auto load_chunk = [&](int c, int s) {
        int koff = c * 64;
        uint32_t abase = sb + s * ABUF;
        uint32_t bbase = sb + 2 * ABUF + s * ABUF;
        #pragma unroll
        for (int i = 0; i < 4; i++) {
            int idx = tid + i * 256;
            int row = idx >> 3, g = idx & 7;
            CP_ASYNC16(abase + SWZ128(row, g), Ablk + (size_t)row * KDIM + koff + g * 8);
        }
        #pragma unroll
        for (int i = 0; i < 4; i++) {
            int idx = tid + i * 256;
            int row = idx >> 3, g = idx & 7;
            CP_ASYNC16(bbase + SWZ128(row, g), Bblk + (size_t)row * KDIM + koff + g * 8);
        }
        CP_COMMIT();
    };

    load_chunk(0, 0);

    for (int c = 0; c < NCHUNK; c++) {
        int s = c & 1;
        if (c + 1 < NCHUNK) { load_chunk(c + 1, s ^ 1); CP_WAIT(1); }
        else                { CP_WAIT(0); }
        __syncthreads();

        uint32_t abase = sb + s * ABUF;
        uint32_t bbase = sb + 2 * ABUF + s * ABUF;
        #pragma unroll
        for (int ks = 0; ks < 4; ks++) {
            uint32_t afr[4][4];
            #pragma unroll
            for (int mi = 0; mi < 4; mi++) {
                int row = wm * 64 + mi * 16 + (lid & 15);
                int g = ks * 2 + (lid >> 4);
                ldmatrix_x4(afr[mi], abase + SWZ128(row, g));
            }
            uint32_t bfr[2][4];
            #pragma unroll
            for (int nf = 0; nf < 2; nf++) {
                int row = wn * 32 + nf * 16 + (lid & 7) + ((lid & 16) >> 1);
                int g = ks * 2 + ((lid & 8) >> 3);
                ldmatrix_x4(bfr[nf], bbase + SWZ128(row, g));
            }
            #pragma unroll
            for (int mi = 0; mi < 4; mi++)
                #pragma unroll
                for (int nj = 0; nj < 4; nj++) {
                    const uint32_t* b = bfr[nj >> 1];
                    mma16816(acc[mi][nj], afr[mi], b[(nj & 1) * 2], b[(nj & 1) * 2 + 1]);
                }
        }
        __syncthreads();
    }

    if (MODE == 1) {
        #pragma unroll
        for (int mi = 0; mi < 4; mi++) {
            int mA = m0 + wm * 64 + mi * 16 + (lid >> 2);
            #pragma unroll
            for (int nj = 0; nj < 4; nj++) {
                int n = n0 + wn * 32 + nj * 8 + 2 * (lid & 3);
                float bx = bias[n], by = bias[n + 1];
                float2 v0 = make_float2(acc[mi][nj][0] + bx, acc[mi][nj][1] + by);
                float2 v1 = make_float2(acc[mi][nj][2] + bx, acc[mi][nj][3] + by);
                float2 r0 = *(const float2*)&resid[(size_t)mA * N + n];
                float2 r1 = *(const float2*)&resid[(size_t)(mA + 8) * N + n];
                v0.x += r0.x; v0.y += r0.y; v1.x += r1.x; v1.y += r1.y;
                *(float2*)&C[(size_t)mA * N + n] = v0;
                *(float2*)&C[(size_t)(mA + 8) * N + n] = v1;
            }
        }
    } else {
        #pragma unroll
        for (int mi = 0; mi < 4; mi++) {
            int mbase = m0 + wm * 64 + mi * 16 + (lid >> 2);
            #pragma unroll
            for (int nj = 0; nj < 4; nj++) {
                int n = n0 + wn * 32 + nj * 8 + 2 * (lid & 3);
                int region = n >> 9;
                int hh = (n & 511) >> 6;
                int d = n & 63;
                float bx = bias[n], by = bias[n + 1];
                #pragma unroll
                for (int rr = 0; rr < 2; rr++) {
                    int m = mbase + rr * 8;
                    int w = m >> 4, b = m & 15;
                    float vx = acc[mi][nj][rr * 2 + 0] + bx;
                    float vy = acc[mi][nj][rr * 2 + 1] + by;
                    size_t off = ((size_t)(b * 8 + hh) * W_LEN + w) * HEAD_DIM + d;
                    if (region == 0) {
                        *(float2*)&g_qf[off] =
                            make_float2(to_tf32(vx * QSCALE), to_tf32(vy * QSCALE));
                    } else if (region == 1) {
                        *(float2*)&g_kf[off] = make_float2(to_tf32(vx), to_tf32(vy));
                    } else {
                        *(__nv_bfloat162*)&g_vh[off] = __floats2bfloat162_rn(vx, vy);
                    }
                }
            }
        }
    }
}

// ------------------------------------------------------------- Attention
// 128 threads (4 warps), 64-query tile, 64-key blocks double-buffered.
// Q tf32 frags hoisted to registers (staged through K buffer); 4 CTAs/SM.
// QK^T tf32 (log2-domain scores), ex2 softmax, PV bf16.
#define AT_K 0                   /* 2 x 16KB fp32 */
#define AT_V 32768               /* 2 x 8KB bf16  */
#define ATTN_SMEM 49152          /* 48KB -> 4 CTAs/SM */

__global__ void __launch_bounds__(128, 4) attn_kernel() {
    extern __shared__ __align__(1024) char smem[];
    uint32_t sb = smem_u32(smem);
    int tid = threadIdx.x;
    int lid = tid & 31, wid = tid >> 5;
    int bh = blockIdx.y;
    int q0 = blockIdx.x * 64;
    size_t gb = (size_t)bh * (W_LEN * HEAD_DIM);

    auto ldK = [&](uint32_t dstbase, int row0) {
        #pragma unroll
        for (int i = 0; i < 8; i++) {
            int idx = tid + i * 128;
            int row = idx >> 4, g = idx & 15;
            CP_ASYNC16(dstbase + SWZ256(row, g),
                       g_kf + gb + (size_t)(row0 + row) * HEAD_DIM + g * 4);
        }
    };
    auto ldV = [&](uint32_t dstbase, int row0) {
        #pragma unroll
        for (int i = 0; i < 4; i++) {
            int idx = tid + i * 128;
            int row = idx >> 3, g = idx & 7;
            CP_ASYNC16(dstbase + SWZ128(row, g),
                       g_vh + gb + (size_t)(row0 + row) * HEAD_DIM + g * 8);
        }
    };

    // ---- stage Q through K-stage-0 region, consume into registers ----
    #pragma unroll
    for (int i = 0; i < 8; i++) {
        int idx = tid + i * 128;
        int row = idx >> 4, g = idx & 15;
        CP_ASYNC16(sb + SWZ256(row, g),
                   g_qf + gb + (size_t)(q0 + row) * HEAD_DIM + g * 4);
    }
    CP_COMMIT();
    CP_WAIT(0);
    __syncthreads();

    uint32_t qfr[8][4];          // tf32 A-frags for 8 k8-steps, persistent
    #pragma unroll
    for (int s8 = 0; s8 < 8; s8++) {
        int row = wid * 16 + ((lid >> 3) & 1) * 8 + (lid & 7);
        int g = s8 * 2 + (lid >> 4);
        ldmatrix_x4(qfr[s8], sb + SWZ256(row, g));
    }
    __syncthreads();

    // ---- start K/V pipeline ----
    ldK(sb + AT_K, 0);
    ldV(sb + AT_V, 0);
    CP_COMMIT();

    float o[8][4];
    #pragma unroll
    for (int i = 0; i < 8; i++)
        #pragma unroll
        for (int j = 0; j < 4; j++) o[i][j] = 0.f;
    float mrow[2] = {-1e30f, -1e30f};
    float lrow[2] = {0.f, 0.f};

    for (int kt = 0; kt < 16; kt++) {
        int s = kt & 1;
        if (kt < 15) {
            int r0 = (kt + 1) * 64;
            ldK(sb + AT_K + (s ^ 1) * 16384, r0);
            ldV(sb + AT_V + (s ^ 1) * 8192, r0);
            CP_COMMIT();
            CP_WAIT(1);
        } else {
            CP_WAIT(0);
        }
        __syncthreads();

        uint32_t kbase = sb + AT_K + s * 16384;
        uint32_t vbase = sb + AT_V + s * 8192;

        // ---- S = Q K^T (tf32, log2-domain scores) ----
        float sc[8][4];
        #pragma unroll
        for (int i = 0; i < 8; i++)
            #pragma unroll
            for (int j = 0; j < 4; j++) sc[i][j] = 0.f;

        #pragma unroll
        for (int s8 = 0; s8 < 8; s8++) {
            #pragma unroll
            for (int nf = 0; nf < 4; nf++) {
                uint32_t bfr[4];
                int row = nf * 16 + ((lid >> 4) << 3) + (lid & 7);
                int g = s8 * 2 + ((lid >> 3) & 1);
                ldmatrix_x4(bfr, kbase + SWZ256(row, g));
                mma_tf32(sc[nf * 2 + 0], qfr[s8], bfr[0], bfr[1]);
                mma_tf32(sc[nf * 2 + 1], qfr[s8], bfr[2], bfr[3]);
            }
        }

        // ---- online softmax (ex2.approx; log2 domain) ----
        float mx0 = -1e30f, mx1 = -1e30f;
        #pragma unroll
        for (int j = 0; j < 8; j++) {
            mx0 = fmaxf(mx0, fmaxf(sc[j][0], sc[j][1]));
            mx1 = fmaxf(mx1, fmaxf(sc[j][2], sc[j][3]));
        }
        #pragma unroll
        for (int ofs = 1; ofs <= 2; ofs <<= 1) {
            mx0 = fmaxf(mx0, __shfl_xor_sync(0xffffffffu, mx0, ofs));
            mx1 = fmaxf(mx1, __shfl_xor_sync(0xffffffffu, mx1, ofs));
        }
        float mn0 = fmaxf(mrow[0], mx0), mn1 = fmaxf(mrow[1], mx1);
        float corr0 = fast_ex2(mrow[0] - mn0), corr1 = fast_ex2(mrow[1] - mn1);
        mrow[0] = mn0; mrow[1] = mn1;

        float sum0 = 0.f, sum1 = 0.f;
        #pragma unroll
        for (int j = 0; j < 8; j++) {
            sc[j][0] = fast_ex2(sc[j][0] - mn0);
            sc[j][1] = fast_ex2(sc[j][1] - mn0);
            sc[j][2] = fast_ex2(sc[j][2] - mn1);
            sc[j][3] = fast_ex2(sc[j][3] - mn1);
            sum0 += sc[j][0] + sc[j][1];
            sum1 += sc[j][2] + sc[j][3];
        }
        #pragma unroll
        for (int ofs = 1; ofs <= 2; ofs <<= 1) {
            sum0 += __shfl_xor_sync(0xffffffffu, sum0, ofs);
            sum1 += __shfl_xor_sync(0xffffffffu, sum1, ofs);
        }
        lrow[0] = lrow[0] * corr0 + sum0;
        lrow[1] = lrow[1] * corr1 + sum1;
        if (__any_sync(0xffffffffu, (corr0 != 1.f) | (corr1 != 1.f))) {
            #pragma unroll
            for (int nd = 0; nd < 8; nd++) {
                o[nd][0] *= corr0; o[nd][1] *= corr0;
                o[nd][2] *= corr1; o[nd][3] *= corr1;
            }
        }

        // ---- P frags (bf16 RN) ----
        uint32_t ph[4][4];
        #pragma unroll
        for (int kc = 0; kc < 4; kc++) {
            int j0 = kc * 2, j1 = kc * 2 + 1;
            ph[kc][0] = pack_bf16(sc[j0][0], sc[j0][1]);
            ph[kc][1] = pack_bf16(sc[j0][2], sc[j0][3]);
            ph[kc][2] = pack_bf16(sc[j1][0], sc[j1][1]);
            ph[kc][3] = pack_bf16(sc[j1][2], sc[j1][3]);
        }

        // ---- O += P V (bf16) ----
        #pragma unroll
        for (int kc = 0; kc < 4; kc++) {
            #pragma unroll
            for (int np = 0; np < 4; np++) {
                uint32_t vhf[4];
                int row = kc * 16 + (lid & 7) + ((lid >> 3) & 1) * 8;
                int c16 = np * 2 + ((lid >> 4) & 1);
                ldmatrix_x4_trans(vhf, vbase + ((row * 128) + (((c16 ^ (row & 7)) & 7) << 4)));
                mma16816(o[np * 2 + 0], ph[kc], vhf[0], vhf[1]);
                mma16816(o[np * 2 + 1], ph[kc], vhf[2], vhf[3]);
            }
        }
        __syncthreads();
    }

    // ---- epilogue: normalize, write bf16 [m][E] ----
    float inv0 = 1.f / lrow[0], inv1 = 1.f / lrow[1];
    int b = bh >> 3, h = bh & 7;
    int r0 = lid >> 2, c0 = (lid & 3) * 2;
    #pragma unroll
    for (int nd = 0; nd < 8; nd++) {
        int col = h * HEAD_DIM + nd * 8 + c0;
        #pragma unroll
        for (int rr = 0; rr < 2; rr++) {
            int w = q0 + wid * 16 + r0 + rr * 8;
            int m = w * BSZ + b;
            float inv = rr ? inv1 : inv0;
            float vx = o[nd][rr * 2 + 0] * inv;
            float vy = o[nd][rr * 2 + 1] * inv;
            *(__nv_bfloat162*)&g_attnh[(size_t)m * EMBED + col] = __floats2bfloat162_rn(vx, vy);
        }
    }
}

// ---------------------------------------------------------------- launcher
extern "C" void kernel_launch(void* const* d_in, const int* in_sizes, int n_in,
                              void* d_out, int out_size) {
    const float* feat  = (const float*)d_in[0];
    const float* in_w  = (const float*)d_in[1];
    const float* in_b  = (const float*)d_in[2];
    const float* out_w = (const float*)d_in[3];
    const float* out_b = (const float*)d_in[4];
    const float* ln_g  = (const float*)d_in[5];
    const float* ln_b  = (const float*)d_in[6];
    float* out = (float*)d_out;

    __nv_bfloat16 *xh, *wh, *owh, *attnh;
    cudaGetSymbolAddress((void**)&xh,    g_xh);
    cudaGetSymbolAddress((void**)&wh,    g_wh);
    cudaGetSymbolAddress((void**)&owh,   g_owh);
    cudaGetSymbolAddress((void**)&attnh, g_attnh);

    cudaFuncSetAttribute(gemm_mma<1>, cudaFuncAttributeMaxDynamicSharedMemorySize, GEMM_SMEM);
    cudaFuncSetAttribute(gemm_mma<2>, cudaFuncAttributeMaxDynamicSharedMemorySize, GEMM_SMEM);
    cudaFuncSetAttribute(attn_kernel, cudaFuncAttributeMaxDynamicSharedMemorySize, ATTN_SMEM);

    // 1. LayerNorm -> bf16
    ln_kernel<<<M_ROWS, 256>>>(feat, ln_g, ln_b);

    // 2. both weight tensors -> bf16 (single launch)
    wconv_kernel<<<(W1 + W2 + 255) / 256, 256>>>(in_w, out_w);

    // 3. QKV projection (bf16 mma) -> q/k tf32 (Q pre-scaled by 0.125*log2e), v bf16
    gemm_mma<2><<<dim3(QKV_N / 128, M_ROWS / 128), 256, GEMM_SMEM>>>(
        xh, wh, in_b, nullptr, nullptr, QKV_N);

    // 4. Attention (4 CTA/SM, Q-frags in regs, tf32 QK, ex2, bf16 PV) -> bf16
    attn_kernel<<<dim3(W_LEN / 64, BSZ * NHEADS), 128, ATTN_SMEM>>>();

    // 5. Out projection (bf16 mma) + bias + residual -> d_out
    gemm_mma<1><<<dim3(EMBED / 128, M_ROWS / 128), 256, GEMM_SMEM>>>(
        attnh, owh, out_b, feat, out, EMBED);
}